// round 12
// baseline (speedup 1.0000x reference)
#include <cuda_runtime.h>
#include <cuda_fp16.h>
#include <cuda_bf16.h>

// SilkNNUE: out[r] = MLP( relu( sum_{k<29} emb[x[r,k]] ) )
// R11: (a) layer2 reads h as LDS.128 broadcast (8 halves/load) -> layer2 h
//          phases 512 -> 128 per warp-batch (the R10 L1 residual)
//      (b) row-pair indices packed 16+16 bits -> gather SHFL count halved
//      w2 kept fp32 (protect rel_err margin).

#define VOCAB 14848
#define EMBD  128
#define WARPS_PER_BLOCK 8
#define ROWS_PER_WARP   8
#define ROWS_PER_BLOCK  (WARPS_PER_BLOCK * ROWS_PER_WARP)
#define FULLMASK 0xffffffffu

typedef unsigned long long ull;

__device__ __half g_embh[VOCAB * EMBD];   // 3.8 MB static scratch

// ---- pre-pass: fp32 emb -> fp16 table ----
__global__ __launch_bounds__(256) void convert_emb_kernel(const float* __restrict__ emb)
{
    const int i = blockIdx.x * 256 + threadIdx.x;       // one per 8 elements
    const float4* p = (const float4*)emb + (size_t)i * 2;
    const float4 a = p[0], b = p[1];
    __half2 h0 = __floats2half2_rn(a.x, a.y);
    __half2 h1 = __floats2half2_rn(a.z, a.w);
    __half2 h2 = __floats2half2_rn(b.x, b.y);
    __half2 h3 = __floats2half2_rn(b.z, b.w);
    uint4 o;
    o.x = *(unsigned*)&h0; o.y = *(unsigned*)&h1;
    o.z = *(unsigned*)&h2; o.w = *(unsigned*)&h3;
    ((uint4*)g_embh)[i] = o;
}

// ---- packed fp32x2 helpers (Blackwell f32x2 pipe) ----
__device__ __forceinline__ ull pack2(float x, float y)
{
    ull v;
    asm("mov.b64 %0, {%1, %2};" : "=l"(v) : "f"(x), "f"(y));
    return v;
}
__device__ __forceinline__ void fadd2(ull& acc, float x, float y)
{
    ull v = pack2(x, y);
    asm("add.rn.f32x2 %0, %0, %1;" : "+l"(acc) : "l"(v));
}
__device__ __forceinline__ void ffma2(ull& acc, ull a, ull b)
{
    asm("fma.rn.f32x2 %0, %1, %2, %0;" : "+l"(acc) : "l"(a), "l"(b));
}
__device__ __forceinline__ ull h2_to_f32x2(unsigned h2bits)
{
    const float2 f = __half22float2(*(const __half2*)&h2bits);
    return pack2(f.x, f.y);
}
__device__ __forceinline__ float2 unpack2(ull acc)
{
    float2 f;
    asm("mov.b64 {%0, %1}, %2;" : "=f"(f.x), "=f"(f.y) : "l"(acc));
    return f;
}

__global__ __launch_bounds__(256, 4) void silk_nnue_kernel(
    const int*   __restrict__ x,     // (nrows, 32) int32, first 29 cols used
    const float* __restrict__ w2,    // (32, 128)
    const float* __restrict__ b2,    // (32,)
    const float* __restrict__ w3,    // (32, 64)
    const float* __restrict__ b3,    // (32,)
    const float* __restrict__ w4,    // (1, 64)
    float*       __restrict__ out,   // (nrows,)
    int nrows)
{
    // w2 packed by k-pairs: w2q[k2*32 + j] = (w2[j][2k2], w2[j][2k2+1])
    __shared__ float2 w2q[64 * 32];                       // 16 KB
    __shared__ float  w3t[64 * 32];                       // 8 KB; w3t[k*32+i]=w3[i*64+k]
    __shared__ float  b2s[32], b3s[32], w4s[64];
    __shared__ __align__(16) __half hsm[WARPS_PER_BLOCK][ROWS_PER_WARP][128]; // 16 KB

    const int tid = threadIdx.x;

    for (int i = tid; i < 64 * 32; i += 256) {
        const int j = i & 31, k2 = i >> 5;
        w2q[i] = make_float2(w2[j * 128 + 2 * k2], w2[j * 128 + 2 * k2 + 1]);
    }
    for (int i = tid; i < 32 * 64; i += 256) {
        const int j = i >> 6, k = i & 63;
        w3t[k * 32 + j] = w3[i];
    }
    if (tid < 32) { b2s[tid] = b2[tid]; b3s[tid] = b3[tid]; }
    if (tid < 64) { w4s[tid] = w4[tid]; }
    __syncthreads();

    const int warp = tid >> 5;
    const int lane = tid & 31;
    const int row0 = blockIdx.x * ROWS_PER_BLOCK + warp * ROWS_PER_WARP;
    if (row0 >= nrows) return;
    const int rlast = nrows - 1;

    const int sub = lane & 15;    // 16B chunk within a 256B fp16 emb row
    const int hi  = lane >> 4;    // which row of a pair this lane gathers

    // ---- index prefetch: pair indices packed 16+16 (VOCAB < 65536) ----
    unsigned myidxp[4];
    #pragma unroll
    for (int p = 0; p < 4; p++) {
        const int ra = min(row0 + 2 * p,     rlast);
        const int rb = min(row0 + 2 * p + 1, rlast);
        const unsigned ia = (unsigned)x[ra * 32 + lane];
        const unsigned ib = (unsigned)x[rb * 32 + lane];
        myidxp[p] = ia | (ib << 16);
    }

    const __half* __restrict__ embh = g_embh;
    const int sel_sh = hi << 4;   // 0 or 16: which packed half this lane uses

    // ---- gather-sum in two passes of 2 row-pairs (acc regs halved) ----
    #pragma unroll
    for (int half = 0; half < 2; half++) {
        ull acc[2][4];
        #pragma unroll
        for (int p2 = 0; p2 < 2; p2++)
            #pragma unroll
            for (int q = 0; q < 4; q++) acc[p2][q] = 0ull;

        #pragma unroll 2
        for (int k = 0; k < 29; k++) {
            #pragma unroll
            for (int p2 = 0; p2 < 2; p2++) {
                const unsigned pk = __shfl_sync(FULLMASK, myidxp[half * 2 + p2], k);
                const int idx = (int)((pk >> sel_sh) & 0xffffu);
                const uint4 v = *(const uint4*)(embh + (size_t)idx * EMBD + sub * 8);
                float2 f;
                f = __half22float2(*(const __half2*)&v.x); fadd2(acc[p2][0], f.x, f.y);
                f = __half22float2(*(const __half2*)&v.y); fadd2(acc[p2][1], f.x, f.y);
                f = __half22float2(*(const __half2*)&v.z); fadd2(acc[p2][2], f.x, f.y);
                f = __half22float2(*(const __half2*)&v.w); fadd2(acc[p2][3], f.x, f.y);
            }
        }

        // ReLU + fp16 stage: lane owns values [sub*8, sub*8+8) of row 2p+hi
        #pragma unroll
        for (int p2 = 0; p2 < 2; p2++) {
            const int row = 2 * (half * 2 + p2) + hi;
            const float2 f0 = unpack2(acc[p2][0]);
            const float2 f1 = unpack2(acc[p2][1]);
            const float2 f2 = unpack2(acc[p2][2]);
            const float2 f3 = unpack2(acc[p2][3]);
            __half2 o0  = __floats2half2_rn(fmaxf(f0.x, 0.f), fmaxf(f0.y, 0.f));
            __half2 o1  = __floats2half2_rn(fmaxf(f1.x, 0.f), fmaxf(f1.y, 0.f));
            __half2 o2h = __floats2half2_rn(fmaxf(f2.x, 0.f), fmaxf(f2.y, 0.f));
            __half2 o3h = __floats2half2_rn(fmaxf(f3.x, 0.f), fmaxf(f3.y, 0.f));
            uint4 st;
            st.x = *(unsigned*)&o0;  st.y = *(unsigned*)&o1;
            st.z = *(unsigned*)&o2h; st.w = *(unsigned*)&o3h;
            *(uint4*)(&hsm[warp][row][sub * 8]) = st;   // STS.128, 16B/lane
        }
    }
    __syncwarp();

    // ---- layer 2: 8-k groups; h via one LDS.128 broadcast per (r, group) ----
    ull s2[ROWS_PER_WARP];
    #pragma unroll
    for (int r = 0; r < ROWS_PER_WARP; r++) s2[r] = 0ull;

    #pragma unroll 2
    for (int k8 = 0; k8 < 16; k8++) {
        ull wv[4];
        #pragma unroll
        for (int q = 0; q < 4; q++) {
            const float2 w = w2q[(k8 * 4 + q) * 32 + lane];   // conflict-free LDS.64
            wv[q] = pack2(w.x, w.y);
        }
        #pragma unroll
        for (int r = 0; r < ROWS_PER_WARP; r++) {
            const uint4 hv = *(const uint4*)(&hsm[warp][r][k8 * 8]); // bcast LDS.128
            ffma2(s2[r], h2_to_f32x2(hv.x), wv[0]);
            ffma2(s2[r], h2_to_f32x2(hv.y), wv[1]);
            ffma2(s2[r], h2_to_f32x2(hv.z), wv[2]);
            ffma2(s2[r], h2_to_f32x2(hv.w), wv[3]);
        }
    }
    float o2[ROWS_PER_WARP];
    #pragma unroll
    for (int r = 0; r < ROWS_PER_WARP; r++) {
        const float2 f = unpack2(s2[r]);
        o2[r] = b2s[lane] + f.x + f.y;
    }

    // ---- layer 3 (fused CReLU), weights amortized over 8 rows ----
    float t0[ROWS_PER_WARP], t1[ROWS_PER_WARP];
    #pragma unroll
    for (int r = 0; r < ROWS_PER_WARP; r++) { t0[r] = 0.f; t1[r] = 0.f; }

    const float* __restrict__ w3p = w3t + lane;
    #pragma unroll 4
    for (int j = 0; j < 32; j++) {
        const float wa = w3p[j * 32];
        const float wb = w3p[(32 + j) * 32];
        #pragma unroll
        for (int r = 0; r < ROWS_PER_WARP; r++) {
            const float t = __shfl_sync(FULLMASK, o2[r], j);
            t0[r] += fmaxf(t, 0.f)  * wa;
            t1[r] += fmaxf(-t, 0.f) * wb;
        }
    }

    // ---- layer 4 (fused CReLU) + warp reduction per row ----
    #pragma unroll
    for (int r = 0; r < ROWS_PER_WARP; r++) {
        const float o3 = b3s[lane] + t0[r] + t1[r];
        float g = fmaxf(o3, 0.f) * w4s[lane] + fmaxf(-o3, 0.f) * w4s[32 + lane];
        #pragma unroll
        for (int off = 16; off; off >>= 1)
            g += __shfl_xor_sync(FULLMASK, g, off);
        if (lane == 0 && (row0 + r) < nrows) out[row0 + r] = g;
    }
}

extern "C" void kernel_launch(void* const* d_in, const int* in_sizes, int n_in,
                              void* d_out, int out_size)
{
    const int*   x   = (const int*)  d_in[0];
    const float* emb = (const float*)d_in[1];
    const float* w2  = (const float*)d_in[2];
    const float* b2  = (const float*)d_in[3];
    const float* w3  = (const float*)d_in[4];
    const float* b3  = (const float*)d_in[5];
    const float* w4  = (const float*)d_in[6];
    float* out = (float*)d_out;

    convert_emb_kernel<<<(VOCAB * EMBD / 8 + 255) / 256, 256>>>(emb);

    const int nrows  = in_sizes[0] / 32;
    const int blocks = (nrows + ROWS_PER_BLOCK - 1) / ROWS_PER_BLOCK;
    silk_nnue_kernel<<<blocks, 256>>>(x, w2, b2, w3, b3, w4, out, nrows);
}

// round 13
// speedup vs baseline: 1.0647x; 1.0647x over previous
#include <cuda_runtime.h>
#include <cuda_fp16.h>
#include <cuda_bf16.h>

// SilkNNUE: out[r] = MLP( relu( sum_{k<29} emb[x[r,k]] ) )
// R12: conversion diet.
//  (a) h staged fp32 in (dynamic) smem -> layer2 has ZERO fp16 converts
//  (b) gather pre-adds emb row pairs with HADD2 before converting (CVTs halved)
//  (c) w3 fp16 + biases in registers to keep smem at 52KB -> 4 CTAs/SM

#define VOCAB 14848
#define EMBD  128
#define WARPS_PER_BLOCK 8
#define ROWS_PER_WARP   8
#define ROWS_PER_BLOCK  (WARPS_PER_BLOCK * ROWS_PER_WARP)
#define FULLMASK 0xffffffffu

typedef unsigned long long ull;

__device__ __half g_embh[VOCAB * EMBD];   // 3.8 MB static scratch

// ---- pre-pass: fp32 emb -> fp16 table ----
__global__ __launch_bounds__(256) void convert_emb_kernel(const float* __restrict__ emb)
{
    const int i = blockIdx.x * 256 + threadIdx.x;       // one per 8 elements
    const float4* p = (const float4*)emb + (size_t)i * 2;
    const float4 a = p[0], b = p[1];
    __half2 h0 = __floats2half2_rn(a.x, a.y);
    __half2 h1 = __floats2half2_rn(a.z, a.w);
    __half2 h2 = __floats2half2_rn(b.x, b.y);
    __half2 h3 = __floats2half2_rn(b.z, b.w);
    uint4 o;
    o.x = *(unsigned*)&h0; o.y = *(unsigned*)&h1;
    o.z = *(unsigned*)&h2; o.w = *(unsigned*)&h3;
    ((uint4*)g_embh)[i] = o;
}

// ---- packed fp32x2 helpers (Blackwell f32x2 pipe) ----
__device__ __forceinline__ ull pack2(float x, float y)
{
    ull v;
    asm("mov.b64 %0, {%1, %2};" : "=l"(v) : "f"(x), "f"(y));
    return v;
}
__device__ __forceinline__ void fadd2(ull& acc, float x, float y)
{
    ull v = pack2(x, y);
    asm("add.rn.f32x2 %0, %0, %1;" : "+l"(acc) : "l"(v));
}
__device__ __forceinline__ void ffma2(ull& acc, ull a, ull b)
{
    asm("fma.rn.f32x2 %0, %1, %2, %0;" : "+l"(acc) : "l"(a), "l"(b));
}
__device__ __forceinline__ float2 unpack2(ull acc)
{
    float2 f;
    asm("mov.b64 {%0, %1}, %2;" : "=f"(f.x), "=f"(f.y) : "l"(acc));
    return f;
}
__device__ __forceinline__ __half2 u2h2(unsigned v) { return *(__half2*)&v; }

// Dynamic smem layout (52 KB -> 4 CTAs/SM incl. reserved)
struct SmemLayout {
    float2  w2q[64 * 32];                         // 16 KB: (w2[j][2k],w2[j][2k+1]) at [k2*32+j]
    __half2 w3q[32 * 32];                         // 4 KB: (w3[i][j], w3[i][32+j]) at [j*32+i]
    float   hsm[WARPS_PER_BLOCK][ROWS_PER_WARP][128];  // 32 KB fp32 h
};

extern __shared__ __align__(16) char smem_raw[];

__global__ __launch_bounds__(256, 4) void silk_nnue_kernel(
    const int*   __restrict__ x,     // (nrows, 32) int32, first 29 cols used
    const float* __restrict__ w2,    // (32, 128)
    const float* __restrict__ b2,    // (32,)
    const float* __restrict__ w3,    // (32, 64)
    const float* __restrict__ b3,    // (32,)
    const float* __restrict__ w4,    // (1, 64)
    float*       __restrict__ out,   // (nrows,)
    int nrows)
{
    SmemLayout* S = (SmemLayout*)smem_raw;
    const int tid = threadIdx.x;

    for (int i = tid; i < 64 * 32; i += 256) {
        const int j = i & 31, k2 = i >> 5;
        S->w2q[i] = make_float2(w2[j * 128 + 2 * k2], w2[j * 128 + 2 * k2 + 1]);
    }
    for (int i = tid; i < 32 * 32; i += 256) {
        const int ii = i & 31, j = i >> 5;      // w3q[j*32+ii]
        S->w3q[i] = __floats2half2_rn(w3[ii * 64 + j], w3[ii * 64 + 32 + j]);
    }

    const int warp = tid >> 5;
    const int lane = tid & 31;

    // biases / w4 in registers (no smem)
    const float b2r = b2[lane];
    const float b3r = b3[lane];
    const float w4a = w4[lane];
    const float w4b = w4[32 + lane];

    __syncthreads();

    const int row0 = blockIdx.x * ROWS_PER_BLOCK + warp * ROWS_PER_WARP;
    if (row0 >= nrows) return;
    const int rlast = nrows - 1;

    const int sub = lane & 15;    // 16B chunk within a 256B fp16 emb row
    const int hi  = lane >> 4;    // which row of a pair this lane gathers

    // ---- index prefetch: pair indices packed 16+16 (VOCAB < 65536) ----
    unsigned myidxp[4];
    #pragma unroll
    for (int p = 0; p < 4; p++) {
        const int ra = min(row0 + 2 * p,     rlast);
        const int rb = min(row0 + 2 * p + 1, rlast);
        const unsigned ia = (unsigned)x[ra * 32 + lane];
        const unsigned ib = (unsigned)x[rb * 32 + lane];
        myidxp[p] = ia | (ib << 16);
    }

    const __half* __restrict__ embh = g_embh;
    const int sel_sh = hi << 4;   // 0 or 16

    // ---- gather-sum, two passes of 2 row-pairs; HADD2 pre-add of k-pairs ----
    #pragma unroll
    for (int half = 0; half < 2; half++) {
        ull acc[2][4];
        #pragma unroll
        for (int p2 = 0; p2 < 2; p2++)
            #pragma unroll
            for (int q = 0; q < 4; q++) acc[p2][q] = 0ull;

        #pragma unroll 1
        for (int k = 0; k < 28; k += 2) {
            #pragma unroll
            for (int p2 = 0; p2 < 2; p2++) {
                const unsigned pk0 = __shfl_sync(FULLMASK, myidxp[half * 2 + p2], k);
                const unsigned pk1 = __shfl_sync(FULLMASK, myidxp[half * 2 + p2], k + 1);
                const int i0 = (int)((pk0 >> sel_sh) & 0xffffu);
                const int i1 = (int)((pk1 >> sel_sh) & 0xffffu);
                const uint4 v0 = *(const uint4*)(embh + (size_t)i0 * EMBD + sub * 8);
                const uint4 v1 = *(const uint4*)(embh + (size_t)i1 * EMBD + sub * 8);
                // fp16 pre-add of the two rows (halves CVT count)
                const __half2 s0 = __hadd2(u2h2(v0.x), u2h2(v1.x));
                const __half2 s1 = __hadd2(u2h2(v0.y), u2h2(v1.y));
                const __half2 s2 = __hadd2(u2h2(v0.z), u2h2(v1.z));
                const __half2 s3 = __hadd2(u2h2(v0.w), u2h2(v1.w));
                float2 f;
                f = __half22float2(s0); fadd2(acc[p2][0], f.x, f.y);
                f = __half22float2(s1); fadd2(acc[p2][1], f.x, f.y);
                f = __half22float2(s2); fadd2(acc[p2][2], f.x, f.y);
                f = __half22float2(s3); fadd2(acc[p2][3], f.x, f.y);
            }
        }
        // leftover k = 28
        #pragma unroll
        for (int p2 = 0; p2 < 2; p2++) {
            const unsigned pk = __shfl_sync(FULLMASK, myidxp[half * 2 + p2], 28);
            const int idx = (int)((pk >> sel_sh) & 0xffffu);
            const uint4 v = *(const uint4*)(embh + (size_t)idx * EMBD + sub * 8);
            float2 f;
            f = __half22float2(u2h2(v.x)); fadd2(acc[p2][0], f.x, f.y);
            f = __half22float2(u2h2(v.y)); fadd2(acc[p2][1], f.x, f.y);
            f = __half22float2(u2h2(v.z)); fadd2(acc[p2][2], f.x, f.y);
            f = __half22float2(u2h2(v.w)); fadd2(acc[p2][3], f.x, f.y);
        }

        // ReLU + fp32 stage: lane owns values [sub*8, sub*8+8) of row 2p+hi
        #pragma unroll
        for (int p2 = 0; p2 < 2; p2++) {
            const int row = 2 * (half * 2 + p2) + hi;
            const float2 f0 = unpack2(acc[p2][0]);
            const float2 f1 = unpack2(acc[p2][1]);
            const float2 f2 = unpack2(acc[p2][2]);
            const float2 f3 = unpack2(acc[p2][3]);
            float4 lo, hi4;
            lo.x  = fmaxf(f0.x, 0.f); lo.y  = fmaxf(f0.y, 0.f);
            lo.z  = fmaxf(f1.x, 0.f); lo.w  = fmaxf(f1.y, 0.f);
            hi4.x = fmaxf(f2.x, 0.f); hi4.y = fmaxf(f2.y, 0.f);
            hi4.z = fmaxf(f3.x, 0.f); hi4.w = fmaxf(f3.y, 0.f);
            float* dst = &S->hsm[warp][row][sub * 8];
            ((float4*)dst)[0] = lo;
            ((float4*)dst)[1] = hi4;
        }
    }
    __syncwarp();

    // ---- layer 2: fp32 h, zero converts; 8-k groups, f32x2 FMA ----
    ull s2[ROWS_PER_WARP];
    #pragma unroll
    for (int r = 0; r < ROWS_PER_WARP; r++) s2[r] = 0ull;

    #pragma unroll 2
    for (int k8 = 0; k8 < 16; k8++) {
        ull wv[4];
        #pragma unroll
        for (int q = 0; q < 4; q++) {
            const float2 w = S->w2q[(k8 * 4 + q) * 32 + lane];  // conflict-free LDS.64
            wv[q] = pack2(w.x, w.y);
        }
        #pragma unroll
        for (int r = 0; r < ROWS_PER_WARP; r++) {
            const float* hp = &S->hsm[warp][r][k8 * 8];
            const float4 h0 = ((const float4*)hp)[0];           // broadcast LDS.128
            const float4 h1 = ((const float4*)hp)[1];
            ffma2(s2[r], pack2(h0.x, h0.y), wv[0]);
            ffma2(s2[r], pack2(h0.z, h0.w), wv[1]);
            ffma2(s2[r], pack2(h1.x, h1.y), wv[2]);
            ffma2(s2[r], pack2(h1.z, h1.w), wv[3]);
        }
    }
    float o2[ROWS_PER_WARP];
    #pragma unroll
    for (int r = 0; r < ROWS_PER_WARP; r++) {
        const float2 f = unpack2(s2[r]);
        o2[r] = b2r + f.x + f.y;
    }

    // ---- layer 3 (fused CReLU), fp16 weight pairs, amortized over 8 rows ----
    float t0[ROWS_PER_WARP], t1[ROWS_PER_WARP];
    #pragma unroll
    for (int r = 0; r < ROWS_PER_WARP; r++) { t0[r] = 0.f; t1[r] = 0.f; }

    #pragma unroll 4
    for (int j = 0; j < 32; j++) {
        const float2 wf = __half22float2(S->w3q[j * 32 + lane]); // LDS.32 + cvt
        #pragma unroll
        for (int r = 0; r < ROWS_PER_WARP; r++) {
            const float t = __shfl_sync(FULLMASK, o2[r], j);
            t0[r] += fmaxf(t, 0.f)  * wf.x;
            t1[r] += fmaxf(-t, 0.f) * wf.y;
        }
    }

    // ---- layer 4 (fused CReLU) + warp reduction per row ----
    #pragma unroll
    for (int r = 0; r < ROWS_PER_WARP; r++) {
        const float o3 = b3r + t0[r] + t1[r];
        float g = fmaxf(o3, 0.f) * w4a + fmaxf(-o3, 0.f) * w4b;
        #pragma unroll
        for (int off = 16; off; off >>= 1)
            g += __shfl_xor_sync(FULLMASK, g, off);
        if (lane == 0 && (row0 + r) < nrows) out[row0 + r] = g;
    }
}

extern "C" void kernel_launch(void* const* d_in, const int* in_sizes, int n_in,
                              void* d_out, int out_size)
{
    const int*   x   = (const int*)  d_in[0];
    const float* emb = (const float*)d_in[1];
    const float* w2  = (const float*)d_in[2];
    const float* b2  = (const float*)d_in[3];
    const float* w3  = (const float*)d_in[4];
    const float* b3  = (const float*)d_in[5];
    const float* w4  = (const float*)d_in[6];
    float* out = (float*)d_out;

    convert_emb_kernel<<<(VOCAB * EMBD / 8 + 255) / 256, 256>>>(emb);

    const int smem_bytes = (int)sizeof(SmemLayout);   // ~52 KB
    cudaFuncSetAttribute(silk_nnue_kernel,
                         cudaFuncAttributeMaxDynamicSharedMemorySize, smem_bytes);

    const int nrows  = in_sizes[0] / 32;
    const int blocks = (nrows + ROWS_PER_BLOCK - 1) / ROWS_PER_BLOCK;
    silk_nnue_kernel<<<blocks, 256, smem_bytes>>>(x, w2, b2, w3, b3, w4, out, nrows);
}

// round 15
// speedup vs baseline: 1.7965x; 1.6873x over previous
#include <cuda_runtime.h>
#include <cuda_fp16.h>

// SilkNNUE: out[r] = MLP( relu( sum_{k<29} emb[x[r,k]] ) )
// R14 = R13 with the required .row.col layout modifiers on mma.sync
// (m16n8k16 f16 MMA is row.col-only; fragment packing already matched it).
//  - layers 2+3 on mma.sync.m16n8k16 (HMMA), hi/lo fp16 split for accuracy
//  - B fragments precomputed in fragment order (no ldmatrix layout risk)
//  - A fragments: direct LDS.32 from stride-136 padded h smem (conflict-free)
//  - 8 valid rows in M=16 via a2a3=a0a1 duplication
//  - layer3 A built in-register from layer2 C fragments (CReLU elementwise)
//  - layer4: quad shfl reduction

#define VOCAB 14848
#define EMBD  128
#define WARPS_PER_BLOCK 8
#define ROWS_PER_WARP   8
#define ROWS_PER_BLOCK  (WARPS_PER_BLOCK * ROWS_PER_WARP)
#define FULLMASK 0xffffffffu
#define HSTRIDE 136   // halves per h row (128 + 8 pad: conflict-free A-frag LDS)

typedef unsigned long long ull;

__device__ __half g_embh[VOCAB * EMBD];   // 3.8 MB static scratch

// ---- pre-pass: fp32 emb -> fp16 table ----
__global__ __launch_bounds__(256) void convert_emb_kernel(const float* __restrict__ emb)
{
    const int i = blockIdx.x * 256 + threadIdx.x;       // one per 8 elements
    const float4* p = (const float4*)emb + (size_t)i * 2;
    const float4 a = p[0], b = p[1];
    __half2 h0 = __floats2half2_rn(a.x, a.y);
    __half2 h1 = __floats2half2_rn(a.z, a.w);
    __half2 h2 = __floats2half2_rn(b.x, b.y);
    __half2 h3 = __floats2half2_rn(b.z, b.w);
    uint4 o;
    o.x = *(unsigned*)&h0; o.y = *(unsigned*)&h1;
    o.z = *(unsigned*)&h2; o.w = *(unsigned*)&h3;
    ((uint4*)g_embh)[i] = o;
}

// ---- packed fp32x2 helpers ----
__device__ __forceinline__ ull pack2(float x, float y)
{
    ull v; asm("mov.b64 %0, {%1, %2};" : "=l"(v) : "f"(x), "f"(y)); return v;
}
__device__ __forceinline__ void fadd2(ull& acc, float x, float y)
{
    ull v = pack2(x, y);
    asm("add.rn.f32x2 %0, %0, %1;" : "+l"(acc) : "l"(v));
}
__device__ __forceinline__ float2 unpack2(ull acc)
{
    float2 f; asm("mov.b64 {%0, %1}, %2;" : "=f"(f.x), "=f"(f.y) : "l"(acc)); return f;
}
__device__ __forceinline__ __half2 u2h2(unsigned v) { return *(__half2*)&v; }
__device__ __forceinline__ unsigned h2u(__half2 h)  { return *(unsigned*)&h; }

// m16n8k16 fp16 MMA (row.col), fp32 accum, C in-place
__device__ __forceinline__ void mma16816(float* c,
    unsigned a0, unsigned a1, unsigned a2, unsigned a3, unsigned b0, unsigned b1)
{
    asm volatile(
        "mma.sync.aligned.m16n8k16.row.col.f32.f16.f16.f32 "
        "{%0,%1,%2,%3}, {%4,%5,%6,%7}, {%8,%9}, {%0,%1,%2,%3};"
        : "+f"(c[0]), "+f"(c[1]), "+f"(c[2]), "+f"(c[3])
        : "r"(a0), "r"(a1), "r"(a2), "r"(a3), "r"(b0), "r"(b1));
}

// split a float pair into fp16 hi + fp16 residual
__device__ __forceinline__ void split2(float x, float y, unsigned& hiu, unsigned& lou)
{
    __half2 hh = __floats2half2_rn(x, y);
    float2 bk = __half22float2(hh);
    __half2 ll = __floats2half2_rn(x - bk.x, y - bk.y);
    hiu = h2u(hh); lou = h2u(ll);
}

struct Smem {
    __half hH[ROWS_PER_BLOCK][HSTRIDE];     // 17408 B: h fp16 hi
    __half hL[ROWS_PER_BLOCK][HSTRIDE];     // 17408 B: h fp16 residual
    uint2  w2fH[8][4][32];                  // 8192 B: w2 B-fragments hi [kb][nb][lane]
    uint2  w2fL[8][4][32];                  // 8192 B: w2 B-fragments lo
    uint2  w3f [4][4][32];                  // 4096 B: w3 B-fragments [kb2][nb][lane]
    float  b2s[32], b3s[32], w4s[64];       // 512 B
};                                           // total ~55.8 KB

extern __shared__ __align__(16) char smem_raw[];

__global__ __launch_bounds__(256, 4) void silk_nnue_kernel(
    const int*   __restrict__ x,     // (nrows, 32) int32, first 29 cols used
    const float* __restrict__ w2,    // (32, 128)
    const float* __restrict__ b2,    // (32,)
    const float* __restrict__ w3,    // (32, 64)
    const float* __restrict__ b3,    // (32,)
    const float* __restrict__ w4,    // (1, 64)
    float*       __restrict__ out,   // (nrows,)
    int nrows)
{
    Smem* S = (Smem*)smem_raw;
    const int tid = threadIdx.x;

    // ---- prologue: fragment-ordered weight tables (explicit PTX mapping) ----
    // B frag (k16 x n8, col-major): b0,b1 = B[k0,k0+1][n], b2,b3 = B[k0+8,k0+9][n];
    // n = nb*8 + t/4, k0 = kb*16 + 2*(t%4). Layer2 B[k][n] = w2[n][k].
    for (int e = tid; e < 8 * 4 * 32; e += 256) {
        const int t = e & 31, nb = (e >> 5) & 3, kb = e >> 7;
        const int n = nb * 8 + (t >> 2), k0 = kb * 16 + 2 * (t & 3);
        const float* wp = w2 + n * 128 + k0;
        const float f0 = wp[0], f1 = wp[1], f2 = wp[8], f3 = wp[9];
        unsigned hA, lA, hB, lB;
        split2(f0, f1, hA, lA);
        split2(f2, f3, hB, lB);
        S->w2fH[kb][nb][t] = make_uint2(hA, hB);
        S->w2fL[kb][nb][t] = make_uint2(lA, lB);
    }
    // Layer3 B[m][i] = w3[i][m] (m = CReLU feature, i = output). fp16 single
    // (w3-fp16 already in error budget since R12).
    for (int e = tid; e < 4 * 4 * 32; e += 256) {
        const int t = e & 31, nb = (e >> 5) & 3, kb2 = e >> 7;
        const int i = nb * 8 + (t >> 2), m0 = kb2 * 16 + 2 * (t & 3);
        const float* wp = w3 + i * 64 + m0;
        S->w3f[kb2][nb][t] = make_uint2(
            h2u(__floats2half2_rn(wp[0], wp[1])),
            h2u(__floats2half2_rn(wp[8], wp[9])));
    }
    if (tid < 32) { S->b2s[tid] = b2[tid]; S->b3s[tid] = b3[tid]; }
    if (tid < 64) { S->w4s[tid] = w4[tid]; }
    __syncthreads();

    const int warp = tid >> 5;
    const int lane = tid & 31;
    const int row0 = blockIdx.x * ROWS_PER_BLOCK + warp * ROWS_PER_WARP;
    if (row0 >= nrows) return;          // warp-uniform
    const int rlast = nrows - 1;

    const int sub = lane & 15;          // 16B chunk within a 256B fp16 emb row
    const int hi  = lane >> 4;          // which row of a pair this lane gathers

    // ---- index prefetch: pair indices packed 16+16 (VOCAB < 65536) ----
    unsigned myidxp[4];
    #pragma unroll
    for (int p = 0; p < 4; p++) {
        const int ra = min(row0 + 2 * p,     rlast);
        const int rb = min(row0 + 2 * p + 1, rlast);
        myidxp[p] = (unsigned)x[ra * 32 + lane] | ((unsigned)x[rb * 32 + lane] << 16);
    }

    const __half* __restrict__ embh = g_embh;
    const int sel_sh = hi << 4;

    // ---- gather-sum, two passes of 2 row-pairs; HADD2 pre-add of k-pairs ----
    #pragma unroll
    for (int ph = 0; ph < 2; ph++) {
        ull acc[2][4];
        #pragma unroll
        for (int p2 = 0; p2 < 2; p2++)
            #pragma unroll
            for (int q = 0; q < 4; q++) acc[p2][q] = 0ull;

        #pragma unroll 1
        for (int k = 0; k < 28; k += 2) {
            #pragma unroll
            for (int p2 = 0; p2 < 2; p2++) {
                const unsigned pk0 = __shfl_sync(FULLMASK, myidxp[ph * 2 + p2], k);
                const unsigned pk1 = __shfl_sync(FULLMASK, myidxp[ph * 2 + p2], k + 1);
                const int i0 = (int)((pk0 >> sel_sh) & 0xffffu);
                const int i1 = (int)((pk1 >> sel_sh) & 0xffffu);
                const uint4 v0 = *(const uint4*)(embh + (size_t)i0 * EMBD + sub * 8);
                const uint4 v1 = *(const uint4*)(embh + (size_t)i1 * EMBD + sub * 8);
                const __half2 s0 = __hadd2(u2h2(v0.x), u2h2(v1.x));
                const __half2 s1 = __hadd2(u2h2(v0.y), u2h2(v1.y));
                const __half2 s2 = __hadd2(u2h2(v0.z), u2h2(v1.z));
                const __half2 s3 = __hadd2(u2h2(v0.w), u2h2(v1.w));
                float2 f;
                f = __half22float2(s0); fadd2(acc[p2][0], f.x, f.y);
                f = __half22float2(s1); fadd2(acc[p2][1], f.x, f.y);
                f = __half22float2(s2); fadd2(acc[p2][2], f.x, f.y);
                f = __half22float2(s3); fadd2(acc[p2][3], f.x, f.y);
            }
        }
        #pragma unroll
        for (int p2 = 0; p2 < 2; p2++) {              // leftover k = 28
            const unsigned pk = __shfl_sync(FULLMASK, myidxp[ph * 2 + p2], 28);
            const int idx = (int)((pk >> sel_sh) & 0xffffu);
            const uint4 v = *(const uint4*)(embh + (size_t)idx * EMBD + sub * 8);
            float2 f;
            f = __half22float2(u2h2(v.x)); fadd2(acc[p2][0], f.x, f.y);
            f = __half22float2(u2h2(v.y)); fadd2(acc[p2][1], f.x, f.y);
            f = __half22float2(u2h2(v.z)); fadd2(acc[p2][2], f.x, f.y);
            f = __half22float2(u2h2(v.w)); fadd2(acc[p2][3], f.x, f.y);
        }

        // ReLU + hi/lo fp16 stage (lane owns [sub*8, sub*8+8) of row 2p+hi)
        #pragma unroll
        for (int p2 = 0; p2 < 2; p2++) {
            const int row = 2 * (ph * 2 + p2) + hi;
            const float2 f0 = unpack2(acc[p2][0]);
            const float2 f1 = unpack2(acc[p2][1]);
            const float2 f2 = unpack2(acc[p2][2]);
            const float2 f3 = unpack2(acc[p2][3]);
            uint4 sH, sL;
            split2(fmaxf(f0.x, 0.f), fmaxf(f0.y, 0.f), sH.x, sL.x);
            split2(fmaxf(f1.x, 0.f), fmaxf(f1.y, 0.f), sH.y, sL.y);
            split2(fmaxf(f2.x, 0.f), fmaxf(f2.y, 0.f), sH.z, sL.z);
            split2(fmaxf(f3.x, 0.f), fmaxf(f3.y, 0.f), sH.w, sL.w);
            *(uint4*)&S->hH[warp * 8 + row][sub * 8] = sH;
            *(uint4*)&S->hL[warp * 8 + row][sub * 8] = sL;
        }
    }
    __syncwarp();

    // ---- layer 2: MMA. A frag: row = lane/4 (dup to rows 8-15), k0 = 2*(lane&3) ----
    float c[4][4];
    #pragma unroll
    for (int nb = 0; nb < 4; nb++)
        #pragma unroll
        for (int q = 0; q < 4; q++) c[nb][q] = 0.f;

    const int rA = warp * 8 + (lane >> 2);
    const int kc = 2 * (lane & 3);
    #pragma unroll
    for (int kb = 0; kb < 8; kb++) {
        const unsigned aH0 = *(const unsigned*)&S->hH[rA][kb * 16 + kc];
        const unsigned aH4 = *(const unsigned*)&S->hH[rA][kb * 16 + kc + 8];
        const unsigned aL0 = *(const unsigned*)&S->hL[rA][kb * 16 + kc];
        const unsigned aL4 = *(const unsigned*)&S->hL[rA][kb * 16 + kc + 8];
        #pragma unroll
        for (int nb = 0; nb < 4; nb++) {
            const uint2 bH = S->w2fH[kb][nb][lane];
            const uint2 bL = S->w2fL[kb][nb][lane];
            mma16816(c[nb], aH0, aH0, aH4, aH4, bH.x, bH.y);  // hi*hi
            mma16816(c[nb], aH0, aH0, aH4, aH4, bL.x, bL.y);  // hi*lo
            mma16816(c[nb], aL0, aL0, aL4, aL4, bH.x, bH.y);  // lo*hi
        }
    }
    // bias: thread holds o2[r=lane/4][j=nb*8+2*(lane&3)+{0,1}] in c[nb][0..1]
    const int jc = 2 * (lane & 3);
    #pragma unroll
    for (int nb = 0; nb < 4; nb++) {
        const float2 bb = *(const float2*)&S->b2s[nb * 8 + jc];
        c[nb][0] += bb.x; c[nb][1] += bb.y;
    }

    // ---- layer 3: A frags built in-register from c via CReLU ----
    // kb2 0: relu(+o2) j0-15 (c[0],c[1]); kb2 1: j16-31 (c[2],c[3]);
    // kb2 2: relu(-o2) j0-15;             kb2 3: relu(-o2) j16-31.
    float d[4][4];
    #pragma unroll
    for (int nb = 0; nb < 4; nb++)
        #pragma unroll
        for (int q = 0; q < 4; q++) d[nb][q] = 0.f;

    #pragma unroll
    for (int kb2 = 0; kb2 < 4; kb2++) {
        const int s0 = (kb2 & 1) * 2, s1 = s0 + 1;
        const float sg = (kb2 < 2) ? 1.f : -1.f;
        const float p0 = fmaxf(sg * c[s0][0], 0.f), p1 = fmaxf(sg * c[s0][1], 0.f);
        const float q0 = fmaxf(sg * c[s1][0], 0.f), q1 = fmaxf(sg * c[s1][1], 0.f);
        unsigned aH0, aL0, aH4, aL4;
        split2(p0, p1, aH0, aL0);
        split2(q0, q1, aH4, aL4);
        #pragma unroll
        for (int nb = 0; nb < 4; nb++) {
            const uint2 b = S->w3f[kb2][nb][lane];
            mma16816(d[nb], aH0, aH0, aH4, aH4, b.x, b.y);
            mma16816(d[nb], aL0, aL0, aL4, aL4, b.x, b.y);
        }
    }

    // ---- layer 4: CReLU dot + quad reduction ----
    float g = 0.f;
    #pragma unroll
    for (int nb = 0; nb < 4; nb++) {
        const float2 b3p = *(const float2*)&S->b3s[nb * 8 + jc];
        const float2 w4p = *(const float2*)&S->w4s[nb * 8 + jc];
        const float2 w4n = *(const float2*)&S->w4s[32 + nb * 8 + jc];
        const float oa = d[nb][0] + b3p.x;
        const float ob = d[nb][1] + b3p.y;
        g += fmaxf(oa, 0.f) * w4p.x + fmaxf(-oa, 0.f) * w4n.x;
        g += fmaxf(ob, 0.f) * w4p.y + fmaxf(-ob, 0.f) * w4n.y;
    }
    g += __shfl_xor_sync(FULLMASK, g, 1);
    g += __shfl_xor_sync(FULLMASK, g, 2);
    if ((lane & 3) == 0) {
        const int row = row0 + (lane >> 2);
        if (row < nrows) out[row] = g;
    }
}

extern "C" void kernel_launch(void* const* d_in, const int* in_sizes, int n_in,
                              void* d_out, int out_size)
{
    const int*   x   = (const int*)  d_in[0];
    const float* emb = (const float*)d_in[1];
    const float* w2  = (const float*)d_in[2];
    const float* b2  = (const float*)d_in[3];
    const float* w3  = (const float*)d_in[4];
    const float* b3  = (const float*)d_in[5];
    const float* w4  = (const float*)d_in[6];
    float* out = (float*)d_out;

    convert_emb_kernel<<<(VOCAB * EMBD / 8 + 255) / 256, 256>>>(emb);

    const int smem_bytes = (int)sizeof(Smem);
    cudaFuncSetAttribute(silk_nnue_kernel,
                         cudaFuncAttributeMaxDynamicSharedMemorySize, smem_bytes);

    const int nrows  = in_sizes[0] / 32;
    const int blocks = (nrows + ROWS_PER_BLOCK - 1) / ROWS_PER_BLOCK;
    silk_nnue_kernel<<<blocks, 256, smem_bytes>>>(x, w2, b2, w3, b3, w4, out, nrows);
}